// round 3
// baseline (speedup 1.0000x reference)
#include <cuda_runtime.h>
#include <cstdint>

// Problem constants (x = [4096, 8192, 1] f32, G = 7)
constexpr int B_ROWS = 4096;
constexpr int I_COLS = 8192;
constexpr int G      = 7;

constexpr int BT    = 512;           // threads per block (2 CTAs/SM)
constexpr int IPT   = 16;            // items per thread
constexpr int NWARP = BT / 32;       // 16 warps
constexpr int NDIG  = 256;           // 8-bit digits
constexpr int NPASS = 4;             // 4 x 8 bits
constexpr int HSTRIDE = NDIG + 1;    // 257: pad to break scan bank conflicts
constexpr int HIST_WORDS = NWARP * HSTRIDE;        // 4112
constexpr int CNT_TOTAL  = NWARP * NDIG;           // 4096 logical counters
constexpr int PER_THREAD = CNT_TOTAL / BT;         // 8

// Dynamic shared memory layout
constexpr size_t OFF_BUF  = ((HIST_WORDS * 4 + 127) / 128) * 128;  // 16512
constexpr size_t OFF_AUX  = OFF_BUF + (size_t)I_COLS * 8;          // +65536
constexpr size_t OFF_SCAL = OFF_AUX + 32 * 4;
constexpr size_t SMEM_BYTES = OFF_SCAL + 16 * 4;                   // ~82.3 KB

__device__ __forceinline__ uint32_t fwd_key(uint32_t b) {
    // ascending sort of this key == descending sort of the float
    uint32_t m = (uint32_t)(((int32_t)b) >> 31) | 0x80000000u;
    return ~(b ^ m);
}
__device__ __forceinline__ float inv_key(uint32_t k) {
    uint32_t u = ~k;
    uint32_t b = (u & 0x80000000u) ? (u ^ 0x80000000u) : ~u;
    return __uint_as_float(b);
}

extern __shared__ unsigned char smem_raw[];

__global__ void __launch_bounds__(BT, 2)
portfolio_radix8_v2(const float* __restrict__ x, float* __restrict__ out)
{
    uint32_t*           hist = (uint32_t*)smem_raw;
    unsigned long long* buf  = (unsigned long long*)(smem_raw + OFF_BUF);
    uint32_t*           aux  = (uint32_t*)(smem_raw + OFF_AUX);
    float*              scal = (float*)(smem_raw + OFF_SCAL);

    const int tid  = threadIdx.x;
    const int wid  = tid >> 5;
    const int lane = tid & 31;
    const unsigned lt_mask = (1u << lane) - 1u;
    const int row  = blockIdx.x;
    const float* xr = x + (size_t)row * I_COLS;

    // Item (w, s, lane) sits at position p = w*512 + s*32 + lane.
    // Processing order (slot asc, lane asc) == position order within a warp;
    // scan orders (digit, warp asc) == position order across warps -> the
    // sort is fully stable (ties -> index ascending), matching jnp.argsort(-x).
    uint32_t key[IPT], val[IPT];
    #pragma unroll
    for (int s = 0; s < IPT; s++) {
        int p = (wid << 9) + (s << 5) + lane;
        key[s] = fwd_key(__float_as_uint(xr[p]));
        val[s] = (uint32_t)p;
    }
    // zero hist for pass 0
    for (int i = tid; i < HIST_WORDS; i += BT) hist[i] = 0;
    __syncthreads();

    #pragma unroll 1
    for (int pass = 0; pass < NPASS; pass++) {
        const int shift = pass * 8;

        // ---- Phase A: per-warp digit histograms (counts only; atomics ->
        //      no cross-slot ordering chain, fully pipelined) ----
        #pragma unroll
        for (int s = 0; s < IPT; s++) {
            uint32_t d    = (key[s] >> shift) & (NDIG - 1);
            unsigned mask = __match_any_sync(0xFFFFFFFFu, d);
            int leader    = __ffs(mask) - 1;
            if (lane == leader)
                atomicAdd(&hist[wid * HSTRIDE + d], (uint32_t)__popc(mask));
        }
        __syncthreads();

        // ---- Phase B: exclusive scan over logical order L = d*NWARP + w ----
        // addr(L) = (L & 15)*HSTRIDE + (L >> 4)
        {
            uint32_t sum = 0;
            #pragma unroll
            for (int i = 0; i < PER_THREAD; i++) {
                int L = tid * PER_THREAD + i;
                sum += hist[(L & (NWARP - 1)) * HSTRIDE + (L >> 4)];
            }
            uint32_t inc = sum;
            #pragma unroll
            for (int o = 1; o < 32; o <<= 1) {
                uint32_t n = __shfl_up_sync(0xFFFFFFFFu, inc, o);
                if (lane >= o) inc += n;
            }
            if (lane == 31) aux[wid] = inc;
            __syncthreads();
            if (wid == 0) {
                uint32_t t  = (lane < NWARP) ? aux[lane] : 0;
                uint32_t ti = t;
                #pragma unroll
                for (int o = 1; o < 32; o <<= 1) {
                    uint32_t n = __shfl_up_sync(0xFFFFFFFFu, ti, o);
                    if (lane >= o) ti += n;
                }
                if (lane < NWARP) aux[lane] = ti - t;  // exclusive warp prefix
            }
            __syncthreads();
            uint32_t run = aux[wid] + (inc - sum);     // exclusive base of my chunk
            #pragma unroll
            for (int i = 0; i < PER_THREAD; i++) {
                int L = tid * PER_THREAD + i;
                uint32_t* a = &hist[(L & (NWARP - 1)) * HSTRIDE + (L >> 4)];
                uint32_t v = *a;
                *a = run;
                run += v;
            }
        }
        __syncthreads();

        // ---- Phase C: serial cursor walk + fused (key|index) scatter ----
        #pragma unroll
        for (int s = 0; s < IPT; s++) {
            uint32_t d    = (key[s] >> shift) & (NDIG - 1);
            unsigned mask = __match_any_sync(0xFFFFFFFFu, d);
            int leader    = __ffs(mask) - 1;
            uint32_t base = 0;
            if (lane == leader) {
                uint32_t* a = &hist[wid * HSTRIDE + d];
                base = *a;
                *a = base + (uint32_t)__popc(mask);
            }
            base = __shfl_sync(0xFFFFFFFFu, base, leader);
            uint32_t pos = base + (uint32_t)__popc(mask & lt_mask);
            buf[pos] = ((unsigned long long)key[s] << 32) | (unsigned long long)val[s];
        }
        __syncthreads();

        // ---- gather back + zero hist for next pass ----
        if (pass < NPASS - 1) {
            #pragma unroll
            for (int s = 0; s < IPT; s++) {
                unsigned long long kv = buf[(wid << 9) + (s << 5) + lane];
                key[s] = (uint32_t)(kv >> 32);
                val[s] = (uint32_t)(kv & 0xFFFFFFFFu);
            }
            for (int i = tid; i < HIST_WORDS; i += BT) hist[i] = 0;
            __syncthreads();
        }
    }

    // ---- epilogue: softmaxes over top-G / bottom-G sorted values ----
    if (tid == 0) {
        float t[G], b[G];
        #pragma unroll
        for (int i = 0; i < G; i++) t[i] = inv_key((uint32_t)(buf[i] >> 32));
        #pragma unroll
        for (int i = 0; i < G; i++) b[i] = inv_key((uint32_t)(buf[I_COLS - G + i] >> 32));

        float m = t[0];
        #pragma unroll
        for (int i = 1; i < G; i++) m = fmaxf(m, t[i]);
        float e[G], s = 0.0f;
        #pragma unroll
        for (int i = 0; i < G; i++) { e[i] = expf(t[i] - m); s += e[i]; }
        float invs = 1.0f / s;
        #pragma unroll
        for (int i = 0; i < G; i++) scal[i] = e[i] * invs;

        float m2 = 1.0f - b[0];
        #pragma unroll
        for (int i = 1; i < G; i++) m2 = fmaxf(m2, 1.0f - b[i]);
        float e2[G], s2 = 0.0f;
        #pragma unroll
        for (int i = 0; i < G; i++) { e2[i] = expf((1.0f - b[i]) - m2); s2 += e2[i]; }
        float invs2 = 1.0f / s2;
        #pragma unroll
        for (int i = 0; i < G; i++) scal[G + i] = -e2[i] * invs2;
    }
    __syncthreads();

    // ---- write b_c and sorted_indices (both f32), fully coalesced ----
    float* bc = out + (size_t)row * I_COLS;
    float* si = out + (size_t)B_ROWS * I_COLS + (size_t)row * I_COLS;
    #pragma unroll
    for (int s = 0; s < IPT; s++) {
        int r = (wid << 9) + (s << 5) + lane;
        unsigned long long kv = buf[r];
        float v = 0.0f;
        if (r < G)                v = scal[r];
        else if (r >= I_COLS - G) v = scal[G + r - (I_COLS - G)];
        bc[r] = v;
        si[r] = (float)(uint32_t)(kv & 0xFFFFFFFFu);
    }
}

extern "C" void kernel_launch(void* const* d_in, const int* in_sizes, int n_in,
                              void* d_out, int out_size)
{
    (void)in_sizes; (void)n_in; (void)out_size;
    const float* x = (const float*)d_in[0];
    float* out = (float*)d_out;

    cudaFuncSetAttribute(portfolio_radix8_v2,
                         cudaFuncAttributeMaxDynamicSharedMemorySize,
                         (int)SMEM_BYTES);
    portfolio_radix8_v2<<<B_ROWS, BT, SMEM_BYTES>>>(x, out);
}

// round 4
// speedup vs baseline: 2.3490x; 2.3490x over previous
#include <cuda_runtime.h>
#include <cub/block/block_radix_sort.cuh>

// Problem constants (match reference: x = [4096, 8192, 1] f32, G = 7)
constexpr int B_ROWS = 4096;
constexpr int I_COLS = 8192;
constexpr int G = 7;

constexpr int BT  = 512;   // threads per block
constexpr int IPT = 16;    // items per thread (BT*IPT == I_COLS)

__global__ void __launch_bounds__(BT, 2)
portfolio_sort_kernel(const float* __restrict__ x, float* __restrict__ out)
{
    using Sorter = cub::BlockRadixSort<float, BT, IPT, int>;
    __shared__ typename Sorter::TempStorage temp;
    __shared__ float s_top[G];   // sorted_x[0:G]       (descending)
    __shared__ float s_bot[G];   // sorted_x[I-G:I]
    __shared__ float s_win[G];   // softmax(top)
    __shared__ float s_los[G];   // -softmax(1 - bot)

    const int row = blockIdx.x;
    const float* xr = x + (size_t)row * I_COLS;

    // Blocked load: thread t owns elements [t*IPT, t*IPT+IPT) -> 4x float4,
    // fully coalesced. Blocked order == original order, so cub's stable radix
    // sort reproduces jnp.argsort(-x) tie-breaking exactly.
    float keys[IPT];
    int   vals[IPT];
    const int base = threadIdx.x * IPT;
    const float4* xr4 = reinterpret_cast<const float4*>(xr + base);
    #pragma unroll
    for (int q = 0; q < IPT / 4; q++) {
        float4 a = xr4[q];
        keys[q * 4 + 0] = a.x;
        keys[q * 4 + 1] = a.y;
        keys[q * 4 + 2] = a.z;
        keys[q * 4 + 3] = a.w;
    }
    #pragma unroll
    for (int i = 0; i < IPT; i++) vals[i] = base + i;

    Sorter(temp).SortDescendingBlockedToStriped(keys, vals);

    // Striped arrangement: item i of thread t holds rank (i*BT + t).
    #pragma unroll
    for (int i = 0; i < IPT; i++) {
        int r = i * BT + threadIdx.x;
        if (r < G)           s_top[r] = keys[i];
        if (r >= I_COLS - G) s_bot[r - (I_COLS - G)] = keys[i];
    }
    __syncthreads();

    if (threadIdx.x == 0) {
        // winner = softmax(sorted_x[:G])
        float m = s_top[0];
        #pragma unroll
        for (int i = 1; i < G; i++) m = fmaxf(m, s_top[i]);
        float e[G], s = 0.0f;
        #pragma unroll
        for (int i = 0; i < G; i++) { e[i] = expf(s_top[i] - m); s += e[i]; }
        float inv = 1.0f / s;
        #pragma unroll
        for (int i = 0; i < G; i++) s_win[i] = e[i] * inv;

        // loser = -softmax(1 - sorted_x[-G:])
        float m2 = 1.0f - s_bot[0];
        #pragma unroll
        for (int i = 1; i < G; i++) m2 = fmaxf(m2, 1.0f - s_bot[i]);
        float e2[G], s2 = 0.0f;
        #pragma unroll
        for (int i = 0; i < G; i++) { e2[i] = expf((1.0f - s_bot[i]) - m2); s2 += e2[i]; }
        float inv2 = 1.0f / s2;
        #pragma unroll
        for (int i = 0; i < G; i++) s_los[i] = -e2[i] * inv2;
    }
    __syncthreads();

    // Output layout: [b_c (B*I f32)] then [sorted_indices (B*I, written as f32)]
    float* bc = out + (size_t)row * I_COLS;
    float* si = out + (size_t)B_ROWS * I_COLS + (size_t)row * I_COLS;
    #pragma unroll
    for (int i = 0; i < IPT; i++) {
        int r = i * BT + threadIdx.x;
        float v = 0.0f;
        if (r < G)                v = s_win[r];
        else if (r >= I_COLS - G) v = s_los[r - (I_COLS - G)];
        bc[r] = v;
        si[r] = (float)vals[i];
    }
}

extern "C" void kernel_launch(void* const* d_in, const int* in_sizes, int n_in,
                              void* d_out, int out_size)
{
    (void)in_sizes; (void)n_in; (void)out_size;
    const float* x = (const float*)d_in[0];
    float* out = (float*)d_out;
    portfolio_sort_kernel<<<B_ROWS, BT>>>(x, out);
}